// round 7
// baseline (speedup 1.0000x reference)
#include <cuda_runtime.h>
#include <cstdint>
#include <cstddef>

#define S_   250
#define N_   200
#define MAXC 16
#define H_   64
#define HID_ 512
#define BN_  32
#define NPED (S_*N_)

// ---- scratch (static __device__ arrays: allocation-free) ----
__device__ __align__(16) static float g_Y[(size_t)NPED * HID_];   // h @ W1[:64] + b1p
__device__               static int   g_sel[NPED * MAXC];         // ranks
__device__ __align__(16) static float g_wpe[2 * HID_];            // W_pos @ W1[64:]
__device__ __align__(16) static float g_b1p[HID_];                // b1 + b_pos @ W1[64:]

// ---- packed f32x2 helpers ----
#define FMA2(d, a, b) asm("fma.rn.f32x2 %0, %1, %2, %0;" : "+l"(d) : "l"(a), "l"(b))
#define PACK_DUP(d, x) asm("mov.b64 %0, {%1, %1};" : "=l"(d) : "f"(x))
#define UNPK(lo, hi, v) asm("mov.b64 {%0, %1}, %2;" : "=f"(lo), "=f"(hi) : "l"(v))

// =====================================================================
// tiny precompute: wpe, folded bias
// =====================================================================
__global__ void prep_kernel(const float* __restrict__ W_pos, const float* __restrict__ b_pos,
                            const float* __restrict__ W1,    const float* __restrict__ b1) {
    int t = threadIdx.x; // 512 threads
    float s0 = 0.f, s1 = 0.f, sb = 0.f;
    for (int e = 0; e < 64; ++e) {
        float w = W1[(size_t)(64 + e) * HID_ + t];
        s0 += W_pos[e] * w;
        s1 += W_pos[64 + e] * w;
        sb += b_pos[e] * w;
    }
    g_wpe[t] = s0;
    g_wpe[HID_ + t] = s1;
    g_b1p[t] = b1[t] + sb;
}

// =====================================================================
// ranks: sel[s,i,m] = #{ j : d_j<d_m or (d_j==d_m and j<m) }  (stable argsort^2)
// =====================================================================
__device__ __forceinline__ float distf(const float* px, const float* py,
                                       int j, float xi, float yi) {
    float dx = px[j] - xi;
    float dy = py[j] - yi;
    return __fsqrt_rn(__fadd_rn(__fmul_rn(dx, dx), __fmul_rn(dy, dy)));
}

__global__ void rank_kernel(const float* __restrict__ lp) {
    int s = blockIdx.y;
    __shared__ float px[N_], py[N_];
    int tid = threadIdx.x;
    for (int j = tid; j < N_; j += 256) {
        px[j] = lp[(size_t)(s * N_ + j) * 2];
        py[j] = lp[(size_t)(s * N_ + j) * 2 + 1];
    }
    __syncthreads();
    int w = tid >> 5, lane = tid & 31;
    int i = blockIdx.x * 8 + w;
    float xi = px[i], yi = py[i];

    float dl = distf(px, py, lane, xi, yi);
    float dm[MAXC];
#pragma unroll
    for (int m = 0; m < MAXC; ++m) dm[m] = __shfl_sync(0xffffffffu, dl, m);

    int cnt[MAXC];
#pragma unroll
    for (int m = 0; m < MAXC; ++m) cnt[m] = 0;
    for (int j = lane; j < N_; j += 32) {
        float d = distf(px, py, j, xi, yi);
#pragma unroll
        for (int m = 0; m < MAXC; ++m)
            cnt[m] += (int)((d < dm[m]) || (d == dm[m] && j < m));
    }
    int myr = 0;
#pragma unroll
    for (int m = 0; m < MAXC; ++m) {
        int tot = __reduce_add_sync(0xffffffffu, cnt[m]);
        if (lane == m) myr = tot;
    }
    if (lane < MAXC) g_sel[(s * N_ + i) * MAXC + lane] = myr;
}

// =====================================================================
// Y = h @ W1[0:64,:] + b1p   (bias folded here; prep runs first)
// =====================================================================
__global__ void y_kernel(const float* __restrict__ h, const float* __restrict__ W1) {
    __shared__ __align__(16) float Ash[64 * 65];
    __shared__ __align__(16) float Bsh[64 * 64];
    int tid = threadIdx.x;
    int row0 = blockIdx.x * 64;
    int c0   = blockIdx.y * 64;
#pragma unroll
    for (int q = 0; q < 4; ++q) {
        int idx4 = tid + 256 * q;
        int row = idx4 >> 4, k4 = (idx4 & 15) << 2;
        float4 v = make_float4(0.f, 0.f, 0.f, 0.f);
        if (row0 + row < NPED) v = *(const float4*)&h[(size_t)(row0 + row) * H_ + k4];
        Ash[row * 65 + k4 + 0] = v.x; Ash[row * 65 + k4 + 1] = v.y;
        Ash[row * 65 + k4 + 2] = v.z; Ash[row * 65 + k4 + 3] = v.w;
    }
#pragma unroll
    for (int q = 0; q < 4; ++q) {
        int idx4 = tid + 256 * q;
        int k = idx4 >> 4, c4 = (idx4 & 15) << 2;
        *(float4*)&Bsh[k * 64 + c4] = *(const float4*)&W1[(size_t)k * HID_ + c0 + c4];
    }
    __syncthreads();
    int rg = tid >> 4, cg = tid & 15;
    float acc[4][4] = {};
#pragma unroll 16
    for (int k = 0; k < 64; ++k) {
        float a[4];
#pragma unroll
        for (int r = 0; r < 4; ++r) a[r] = Ash[(rg * 4 + r) * 65 + k];
        float4 b = *(const float4*)&Bsh[k * 64 + cg * 4];
#pragma unroll
        for (int r = 0; r < 4; ++r) {
            acc[r][0] += a[r] * b.x; acc[r][1] += a[r] * b.y;
            acc[r][2] += a[r] * b.z; acc[r][3] += a[r] * b.w;
        }
    }
    float4 bb = *(const float4*)&g_b1p[c0 + cg * 4];
#pragma unroll
    for (int r = 0; r < 4; ++r) {
        int row = row0 + rg * 4 + r;
        if (row < NPED)
            *(float4*)&g_Y[(size_t)row * HID_ + c0 + cg * 4] =
                make_float4(acc[r][0] + bb.x, acc[r][1] + bb.y,
                            acc[r][2] + bb.z, acc[r][3] + bb.w);
    }
}

// =====================================================================
// fused: gather + in-register layer1 + f32x2 layer2 GEMM + attention pool
// block = (s, 16 peds) -> 256 rows x 32 cols; 128 thr.
// thread: 4 rows x 16 cols (half = tid>>6 picks col half; warp-uniform ->
// W2 LDS stays broadcast).  W2 resident in smem; barrier-free mainloop.
// =====================================================================
#define O_W2   0        // 16384 (reused by X2 256x33=8448 + wsh 256)
#define O_WP0  16384    // 512
#define O_WP1  16896    // 512
#define O_PX   17408    // 200
#define O_PY   17608    // 200
#define O_B2   17808    // 32
#define O_BAT  17840    // 16
#define SM_FLOATS 17856

__global__ __launch_bounds__(128) void fused_kernel(
    const float* __restrict__ lp, const float* __restrict__ W2g,
    const float* __restrict__ b2g, const float* __restrict__ Wag,
    const float* __restrict__ bag, float* __restrict__ out) {
    extern __shared__ __align__(16) float sm[];
    float* W2s  = sm + O_W2;
    float* wp0s = sm + O_WP0;
    float* wp1s = sm + O_WP1;
    float* px   = sm + O_PX;
    float* py   = sm + O_PY;
    float* b2s  = sm + O_B2;
    float* bats = sm + O_BAT;

    const int tid = threadIdx.x;
    const int s   = blockIdx.y;
    const int pg  = blockIdx.x;          // 16-ped group (0..12, last partial)
    const int base = s * N_;

    // ---- stage constants ----
#pragma unroll
    for (int q = 0; q < 32; ++q)   // W2: 4096 float4
        *(float4*)&W2s[(tid + q * 128) * 4] = *(const float4*)&W2g[(size_t)(tid + q * 128) * 4];
    for (int k = tid; k < HID_; k += 128) {
        wp0s[k] = g_wpe[k];
        wp1s[k] = g_wpe[HID_ + k];
    }
    for (int j = tid; j < N_; j += 128) {
        float2 p = *(const float2*)&lp[(size_t)(base + j) * 2];
        px[j] = p.x; py[j] = p.y;
    }
    if (tid < BN_)  b2s[tid]  = b2g[tid];
    if (tid < MAXC) bats[tid] = bag[tid];
    __syncthreads();

    // ---- per-thread tile: rows 4g..4g+3 (same ped), cols half*16..+16 ----
    const int half = tid >> 6;           // warps 0,1 -> half 0; warps 2,3 -> half 1
    const int g    = tid & 63;
    const float* yp[4];
    float fx[4], fy[4];
    {
        int ped = g >> 2, m0 = (g & 3) << 2;
        int ig = min(pg * 16 + ped, N_ - 1);
        int4 rk = *(const int4*)&g_sel[(base + ig) * MAXC + m0];
        int rr[4] = {rk.x, rk.y, rk.z, rk.w};
        float xi = px[ig], yi = py[ig];
#pragma unroll
        for (int r = 0; r < 4; ++r) {
            yp[r] = g_Y + (size_t)(base + rr[r]) * HID_;
            fx[r] = px[rr[r]] - xi;
            fy[r] = py[rr[r]] - yi;
        }
    }
    const float* w2base = W2s + half * 16;

    unsigned long long acc[4][8];
#pragma unroll
    for (int r = 0; r < 4; ++r)
#pragma unroll
        for (int q = 0; q < 8; ++q) acc[r][q] = 0ULL;

    // ---- mainloop: K=512, barrier-free ----
#pragma unroll 1
    for (int k = 0; k < HID_; k += 4) {
        float4 w0 = *(const float4*)&wp0s[k];
        float4 w1 = *(const float4*)&wp1s[k];
        float x[4][4];
#pragma unroll
        for (int r = 0; r < 4; ++r) {
            float4 y = *(const float4*)(yp[r] + k);    // bias pre-folded
            x[r][0] = fmaxf(fmaf(fx[r], w0.x, fmaf(fy[r], w1.x, y.x)), 0.f);
            x[r][1] = fmaxf(fmaf(fx[r], w0.y, fmaf(fy[r], w1.y, y.y)), 0.f);
            x[r][2] = fmaxf(fmaf(fx[r], w0.z, fmaf(fy[r], w1.z, y.z)), 0.f);
            x[r][3] = fmaxf(fmaf(fx[r], w0.w, fmaf(fy[r], w1.w, y.w)), 0.f);
        }
#pragma unroll
        for (int kk = 0; kk < 4; ++kk) {
            const float* wr = w2base + (k + kk) * 32;
            ulonglong2 p0 = *(const ulonglong2*)(wr);
            ulonglong2 p1 = *(const ulonglong2*)(wr + 4);
            ulonglong2 p2 = *(const ulonglong2*)(wr + 8);
            ulonglong2 p3 = *(const ulonglong2*)(wr + 12);
#pragma unroll
            for (int r = 0; r < 4; ++r) {
                unsigned long long a;
                PACK_DUP(a, x[r][kk]);
                FMA2(acc[r][0], a, p0.x); FMA2(acc[r][1], a, p0.y);
                FMA2(acc[r][2], a, p1.x); FMA2(acc[r][3], a, p1.y);
                FMA2(acc[r][4], a, p2.x); FMA2(acc[r][5], a, p2.y);
                FMA2(acc[r][6], a, p3.x); FMA2(acc[r][7], a, p3.y);
            }
        }
    }

    __syncthreads();   // all W2s reads done -> safe to overwrite with X2

    // ---- X2 = relu(acc + b2), stride 33 ----
    float* X2  = sm;           // 256*33 = 8448
    float* wsh = sm + 8448;    // 256
#pragma unroll
    for (int r = 0; r < 4; ++r) {
        int row = g * 4 + r;
#pragma unroll
        for (int q = 0; q < 8; ++q) {
            float lo, hi;
            UNPK(lo, hi, acc[r][q]);
            int c = half * 16 + 2 * q;
            X2[row * 33 + c]     = fmaxf(lo + b2s[c], 0.f);
            X2[row * 33 + c + 1] = fmaxf(hi + b2s[c + 1], 0.f);
        }
    }
    __syncthreads();

    // ---- logits + softmax (two peds per thread: p and p+8) ----
    {
        int p = tid >> 4, t = tid & 15;
        float lg0 = bats[t], lg1 = bats[t];
        const float* wa = Wag + t;
#pragma unroll 4
        for (int k = 0; k < 512; ++k) {
            int m = k >> 5, c = k & 31;
            float w = __ldg(&wa[k * 16]);
            lg0 = fmaf(X2[(p * 16 + m) * 33 + c], w, lg0);
            lg1 = fmaf(X2[((p + 8) * 16 + m) * 33 + c], w, lg1);
        }
        float mx0 = lg0, mx1 = lg1;
#pragma unroll
        for (int o = 8; o; o >>= 1) {
            mx0 = fmaxf(mx0, __shfl_xor_sync(0xffffffffu, mx0, o, 16));
            mx1 = fmaxf(mx1, __shfl_xor_sync(0xffffffffu, mx1, o, 16));
        }
        float e0 = expf(lg0 - mx0), e1 = expf(lg1 - mx1);
        float s0 = e0, s1 = e1;
#pragma unroll
        for (int o = 8; o; o >>= 1) {
            s0 += __shfl_xor_sync(0xffffffffu, s0, o, 16);
            s1 += __shfl_xor_sync(0xffffffffu, s1, o, 16);
        }
        wsh[p * 16 + t]       = e0 / s0;
        wsh[(p + 8) * 16 + t] = e1 / s1;
    }
    __syncthreads();

    // ---- weighted pool: 16 peds x 32 cols ----
    for (int o = tid; o < 512; o += 128) {
        int pp = o >> 5, c = o & 31;
        int gp = pg * 16 + pp;
        if (gp < N_) {
            float a = 0.f;
#pragma unroll
            for (int m = 0; m < MAXC; ++m)
                a = fmaf(X2[(pp * 16 + m) * 33 + c], wsh[pp * 16 + m], a);
            out[(size_t)(base + gp) * BN_ + c] = a;
        }
    }
}

extern "C" void kernel_launch(void* const* d_in, const int* in_sizes, int n_in,
                              void* d_out, int out_size) {
    const float* h_st  = (const float*)d_in[0];
    const float* lp    = (const float*)d_in[1];
    const float* W_pos = (const float*)d_in[2];
    const float* b_pos = (const float*)d_in[3];
    const float* W1    = (const float*)d_in[4];
    const float* b1    = (const float*)d_in[5];
    const float* W2    = (const float*)d_in[6];
    const float* b2    = (const float*)d_in[7];
    const float* Wa    = (const float*)d_in[8];
    const float* ba    = (const float*)d_in[9];
    float* out = (float*)d_out;

    cudaFuncSetAttribute(fused_kernel, cudaFuncAttributeMaxDynamicSharedMemorySize,
                         SM_FLOATS * (int)sizeof(float));

    prep_kernel<<<1, HID_>>>(W_pos, b_pos, W1, b1);          // before y_kernel (b1p fold)
    rank_kernel<<<dim3(N_ / 8, S_), 256>>>(lp);
    y_kernel<<<dim3((NPED + 63) / 64, HID_ / 64), 256>>>(h_st, W1);
    fused_kernel<<<dim3(13, S_), 128, SM_FLOATS * (int)sizeof(float)>>>(
        lp, W2, b2, Wa, ba, out);
}

// round 9
// speedup vs baseline: 1.3491x; 1.3491x over previous
#include <cuda_runtime.h>
#include <cstdint>
#include <cstddef>

#define S_   250
#define N_   200
#define MAXC 16
#define H_   64
#define HID_ 512
#define BN_  32
#define NPED (S_*N_)

// ---- scratch (static __device__ arrays: allocation-free) ----
__device__ __align__(16) static float g_Y[(size_t)NPED * HID_];   // h @ W1[:64] + b1p
__device__               static int   g_sel[NPED * MAXC];         // ranks
__device__ __align__(16) static float g_wpe[2 * HID_];            // W_pos @ W1[64:]
__device__ __align__(16) static float g_b1p[HID_];                // b1 + b_pos @ W1[64:]

// ---- packed f32x2 helpers ----
#define FMA2(d, a, b) asm("fma.rn.f32x2 %0, %1, %2, %0;" : "+l"(d) : "l"(a), "l"(b))
#define PACK_DUP(d, x) asm("mov.b64 %0, {%1, %1};" : "=l"(d) : "f"(x))
#define UNPK(lo, hi, v) asm("mov.b64 {%0, %1}, %2;" : "=f"(lo), "=f"(hi) : "l"(v))

__global__ void prep_kernel(const float* __restrict__ W_pos, const float* __restrict__ b_pos,
                            const float* __restrict__ W1,    const float* __restrict__ b1) {
    int t = threadIdx.x; // 512 threads
    float s0 = 0.f, s1 = 0.f, sb = 0.f;
    for (int e = 0; e < 64; ++e) {
        float w = W1[(size_t)(64 + e) * HID_ + t];
        s0 += W_pos[e] * w;
        s1 += W_pos[64 + e] * w;
        sb += b_pos[e] * w;
    }
    g_wpe[t] = s0;
    g_wpe[HID_ + t] = s1;
    g_b1p[t] = b1[t] + sb;
}

__device__ __forceinline__ float distf(const float* px, const float* py,
                                       int j, float xi, float yi) {
    float dx = px[j] - xi;
    float dy = py[j] - yi;
    return __fsqrt_rn(__fadd_rn(__fmul_rn(dx, dx), __fmul_rn(dy, dy)));
}

__global__ void rank_kernel(const float* __restrict__ lp) {
    int s = blockIdx.y;
    __shared__ float px[N_], py[N_];
    int tid = threadIdx.x;
    for (int j = tid; j < N_; j += 256) {
        px[j] = lp[(size_t)(s * N_ + j) * 2];
        py[j] = lp[(size_t)(s * N_ + j) * 2 + 1];
    }
    __syncthreads();
    int w = tid >> 5, lane = tid & 31;
    int i = blockIdx.x * 8 + w;
    float xi = px[i], yi = py[i];

    float dl = distf(px, py, lane, xi, yi);
    float dm[MAXC];
#pragma unroll
    for (int m = 0; m < MAXC; ++m) dm[m] = __shfl_sync(0xffffffffu, dl, m);

    int cnt[MAXC];
#pragma unroll
    for (int m = 0; m < MAXC; ++m) cnt[m] = 0;
    for (int j = lane; j < N_; j += 32) {
        float d = distf(px, py, j, xi, yi);
#pragma unroll
        for (int m = 0; m < MAXC; ++m)
            cnt[m] += (int)((d < dm[m]) || (d == dm[m] && j < m));
    }
    int myr = 0;
#pragma unroll
    for (int m = 0; m < MAXC; ++m) {
        int tot = __reduce_add_sync(0xffffffffu, cnt[m]);
        if (lane == m) myr = tot;
    }
    if (lane < MAXC) g_sel[(s * N_ + i) * MAXC + lane] = myr;
}

__global__ void y_kernel(const float* __restrict__ h, const float* __restrict__ W1) {
    __shared__ __align__(16) float Ash[64 * 65];
    __shared__ __align__(16) float Bsh[64 * 64];
    int tid = threadIdx.x;
    int row0 = blockIdx.x * 64;
    int c0   = blockIdx.y * 64;
#pragma unroll
    for (int q = 0; q < 4; ++q) {
        int idx4 = tid + 256 * q;
        int row = idx4 >> 4, k4 = (idx4 & 15) << 2;
        float4 v = make_float4(0.f, 0.f, 0.f, 0.f);
        if (row0 + row < NPED) v = *(const float4*)&h[(size_t)(row0 + row) * H_ + k4];
        Ash[row * 65 + k4 + 0] = v.x; Ash[row * 65 + k4 + 1] = v.y;
        Ash[row * 65 + k4 + 2] = v.z; Ash[row * 65 + k4 + 3] = v.w;
    }
#pragma unroll
    for (int q = 0; q < 4; ++q) {
        int idx4 = tid + 256 * q;
        int k = idx4 >> 4, c4 = (idx4 & 15) << 2;
        *(float4*)&Bsh[k * 64 + c4] = *(const float4*)&W1[(size_t)k * HID_ + c0 + c4];
    }
    __syncthreads();
    int rg = tid >> 4, cg = tid & 15;
    float acc[4][4] = {};
#pragma unroll 16
    for (int k = 0; k < 64; ++k) {
        float a[4];
#pragma unroll
        for (int r = 0; r < 4; ++r) a[r] = Ash[(rg * 4 + r) * 65 + k];
        float4 b = *(const float4*)&Bsh[k * 64 + cg * 4];
#pragma unroll
        for (int r = 0; r < 4; ++r) {
            acc[r][0] += a[r] * b.x; acc[r][1] += a[r] * b.y;
            acc[r][2] += a[r] * b.z; acc[r][3] += a[r] * b.w;
        }
    }
    float4 bb = *(const float4*)&g_b1p[c0 + cg * 4];
#pragma unroll
    for (int r = 0; r < 4; ++r) {
        int row = row0 + rg * 4 + r;
        if (row < NPED)
            *(float4*)&g_Y[(size_t)row * HID_ + c0 + cg * 4] =
                make_float4(acc[r][0] + bb.x, acc[r][1] + bb.y,
                            acc[r][2] + bb.z, acc[r][3] + bb.w);
    }
}

// =====================================================================
// fused: chunked pipeline; coalesced gather -> X1T smem -> f32x2 GEMM
// =====================================================================
#define KC     32
#define X1TS   257
#define O_X1T  0
#define O_W2C  8704
#define O_WP0  9728
#define O_WP1  10240
#define O_PX   10752
#define O_PY   10952
#define O_FX   11152
#define O_FY   11408
#define O_YR   11664
#define O_B2   11920
#define O_BAT  11952
#define SM_FLOATS 11968

__global__ __launch_bounds__(128, 4) void fused_kernel(
    const float* __restrict__ lp, const float* __restrict__ W2g,
    const float* __restrict__ b2g, const float* __restrict__ Wag,
    const float* __restrict__ bag, float* __restrict__ out) {
    extern __shared__ __align__(16) float sm[];
    float* X1T  = sm + O_X1T;
    float* W2c  = sm + O_W2C;
    float* wp0s = sm + O_WP0;
    float* wp1s = sm + O_WP1;
    float* px   = sm + O_PX;
    float* py   = sm + O_PY;
    float* fxs  = sm + O_FX;
    float* fys  = sm + O_FY;
    int*   yr   = (int*)(sm + O_YR);
    float* b2s  = sm + O_B2;
    float* bats = sm + O_BAT;

    const int tid  = threadIdx.x;
    const int w    = tid >> 5, lane = tid & 31;
    const int s    = blockIdx.y;
    const int pg   = blockIdx.x;
    const int base = s * N_;

    for (int k = tid; k < HID_; k += 128) {
        wp0s[k] = g_wpe[k];
        wp1s[k] = g_wpe[HID_ + k];
    }
    for (int j = tid; j < N_; j += 128) {
        float2 p = *(const float2*)&lp[(size_t)(base + j) * 2];
        px[j] = p.x; py[j] = p.y;
    }
    if (tid < BN_)  b2s[tid]  = b2g[tid];
    if (tid < MAXC) bats[tid] = bag[tid];
    __syncthreads();

    for (int o = tid; o < 256; o += 128) {
        int ped = o >> 4, m = o & 15;
        int ig = min(pg * 16 + ped, N_ - 1);
        int rk = g_sel[(base + ig) * MAXC + m];
        yr[o]  = base + rk;
        fxs[o] = px[rk] - px[ig];
        fys[o] = py[rk] - py[ig];
    }
    __syncthreads();

    unsigned long long acc0[16], acc1[16];
#pragma unroll
    for (int q = 0; q < 16; ++q) {
        unsigned long long b = *(const unsigned long long*)&b2s[2 * q];
        acc0[q] = b; acc1[q] = b;
    }

    const int r_in = w * 64 + (lane >> 3);
    const int k4   = (lane & 7) << 2;

    for (int c = 0; c < 16; ++c) {
        const int k0 = c * KC;
        float4 wv0 = *(const float4*)&wp0s[k0 + k4];
        float4 wv1 = *(const float4*)&wp1s[k0 + k4];
#pragma unroll
        for (int rr = 0; rr < 16; ++rr) {
            int r = r_in + rr * 4;
            float4 y = *(const float4*)&g_Y[(size_t)yr[r] * HID_ + k0 + k4];
            float fx = fxs[r], fy = fys[r];
            X1T[(k4 + 0) * X1TS + r] = fmaxf(fmaf(fx, wv0.x, fmaf(fy, wv1.x, y.x)), 0.f);
            X1T[(k4 + 1) * X1TS + r] = fmaxf(fmaf(fx, wv0.y, fmaf(fy, wv1.y, y.y)), 0.f);
            X1T[(k4 + 2) * X1TS + r] = fmaxf(fmaf(fx, wv0.z, fmaf(fy, wv1.z, y.z)), 0.f);
            X1T[(k4 + 3) * X1TS + r] = fmaxf(fmaf(fx, wv0.w, fmaf(fy, wv1.w, y.w)), 0.f);
        }
        *(float4*)&W2c[tid * 4]         = *(const float4*)&W2g[(size_t)k0 * 32 + tid * 4];
        *(float4*)&W2c[(tid + 128) * 4] = *(const float4*)&W2g[(size_t)k0 * 32 + (tid + 128) * 4];
        __syncthreads();

#pragma unroll 4
        for (int kk = 0; kk < KC; ++kk) {
            float x0 = X1T[kk * X1TS + tid];
            float x1 = X1T[kk * X1TS + tid + 128];
            unsigned long long a0, a1;
            PACK_DUP(a0, x0);
            PACK_DUP(a1, x1);
            const ulonglong2* wr = (const ulonglong2*)&W2c[kk * 32];
#pragma unroll
            for (int q = 0; q < 8; ++q) {
                ulonglong2 b = wr[q];          // cols 4q..4q+3, broadcast LDS.128
                FMA2(acc0[2 * q],     a0, b.x);
                FMA2(acc0[2 * q + 1], a0, b.y);
                FMA2(acc1[2 * q],     a1, b.x);
                FMA2(acc1[2 * q + 1], a1, b.y);
            }
        }
        __syncthreads();
    }

    float* X2  = sm;           // 256*33 = 8448
    float* wsh = sm + 8448;    // 256
#pragma unroll
    for (int q = 0; q < 16; ++q) {
        float lo, hi;
        UNPK(lo, hi, acc0[q]);
        X2[tid * 33 + 2 * q]     = fmaxf(lo, 0.f);
        X2[tid * 33 + 2 * q + 1] = fmaxf(hi, 0.f);
        UNPK(lo, hi, acc1[q]);
        X2[(tid + 128) * 33 + 2 * q]     = fmaxf(lo, 0.f);
        X2[(tid + 128) * 33 + 2 * q + 1] = fmaxf(hi, 0.f);
    }
    __syncthreads();

    {
        int p = tid >> 4, t = tid & 15;
        float lg0 = bats[t], lg1 = bats[t];
        const float* wa = Wag + t;
#pragma unroll 4
        for (int k = 0; k < 512; ++k) {
            int m = k >> 5, cc = k & 31;
            float wv = __ldg(&wa[k * 16]);
            lg0 = fmaf(X2[(p * 16 + m) * 33 + cc], wv, lg0);
            lg1 = fmaf(X2[((p + 8) * 16 + m) * 33 + cc], wv, lg1);
        }
        float mx0 = lg0, mx1 = lg1;
#pragma unroll
        for (int o = 8; o; o >>= 1) {
            mx0 = fmaxf(mx0, __shfl_xor_sync(0xffffffffu, mx0, o, 16));
            mx1 = fmaxf(mx1, __shfl_xor_sync(0xffffffffu, mx1, o, 16));
        }
        float e0 = expf(lg0 - mx0), e1 = expf(lg1 - mx1);
        float s0 = e0, s1 = e1;
#pragma unroll
        for (int o = 8; o; o >>= 1) {
            s0 += __shfl_xor_sync(0xffffffffu, s0, o, 16);
            s1 += __shfl_xor_sync(0xffffffffu, s1, o, 16);
        }
        wsh[p * 16 + t]       = e0 / s0;
        wsh[(p + 8) * 16 + t] = e1 / s1;
    }
    __syncthreads();

    for (int o = tid; o < 512; o += 128) {
        int pp = o >> 5, cc = o & 31;
        int gp = pg * 16 + pp;
        if (gp < N_) {
            float a = 0.f;
#pragma unroll
            for (int m = 0; m < MAXC; ++m)
                a = fmaf(X2[(pp * 16 + m) * 33 + cc], wsh[pp * 16 + m], a);
            out[(size_t)(base + gp) * BN_ + cc] = a;
        }
    }
}

extern "C" void kernel_launch(void* const* d_in, const int* in_sizes, int n_in,
                              void* d_out, int out_size) {
    const float* h_st  = (const float*)d_in[0];
    const float* lp    = (const float*)d_in[1];
    const float* W_pos = (const float*)d_in[2];
    const float* b_pos = (const float*)d_in[3];
    const float* W1    = (const float*)d_in[4];
    const float* b1    = (const float*)d_in[5];
    const float* W2    = (const float*)d_in[6];
    const float* b2    = (const float*)d_in[7];
    const float* Wa    = (const float*)d_in[8];
    const float* ba    = (const float*)d_in[9];
    float* out = (float*)d_out;

    cudaFuncSetAttribute(fused_kernel, cudaFuncAttributeMaxDynamicSharedMemorySize,
                         SM_FLOATS * (int)sizeof(float));

    prep_kernel<<<1, HID_>>>(W_pos, b_pos, W1, b1);
    rank_kernel<<<dim3(N_ / 8, S_), 256>>>(lp);
    y_kernel<<<dim3((NPED + 63) / 64, HID_ / 64), 256>>>(h_st, W1);
    fused_kernel<<<dim3(13, S_), 128, SM_FLOATS * (int)sizeof(float)>>>(
        lp, W2, b2, Wa, ba, out);
}